// round 13
// baseline (speedup 1.0000x reference)
#include <cuda_runtime.h>
#include <cstdint>

#define NN 50000
#define NE 500000
#define HH 128

// ---------------- scratch (device globals; no cudaMalloc allowed) ----------------
__device__ float g_U[NN * HH];
__device__ float g_V[NN * HH];
__device__ float g_S[NN * HH];          // segment sum of relu(h)
__device__ float g_INTRA[NN * HH];
__device__ float g_HID[NN * 2 * HH];
__device__ float g_XA[NN * HH];
__device__ float g_XB[NN * HH];
__device__ float g_POS[NN * 3];
__device__ float g_POSACC[NN * 3];
__device__ float g_DEG[NN];
__device__ float g_DINV[NN];
__device__ float g_BMASK[NN];
__device__ float g_C[HH * 256];         // W2 @ aW1
__device__ float g_D[256];              // b2 @ aW1 + ab1
__device__ int   g_SRC[NE];
__device__ int   g_DST[NE];

// ---------------- mma helper (raw fp32 bits; tf32 HW truncates mantissa) ----------
__device__ __forceinline__ void mma8(float c[4],
                                     unsigned a0, unsigned a1, unsigned a2, unsigned a3,
                                     unsigned b0, unsigned b1) {
    asm("mma.sync.aligned.m16n8k8.row.col.f32.tf32.tf32.f32 "
        "{%0,%1,%2,%3},{%4,%5,%6,%7},{%8,%9},{%0,%1,%2,%3};"
        : "+f"(c[0]), "+f"(c[1]), "+f"(c[2]), "+f"(c[3])
        : "r"(a0), "r"(a1), "r"(a2), "r"(a3), "r"(b0), "r"(b1));
}

// -------- index normalization: handles harness storing edge_index as int32 OR int64
__global__ void convert_idx(const int* __restrict__ ei32, int* __restrict__ SRC,
                            int* __restrict__ DST)
{
    bool is64 = (ei32[1] == 0 && ei32[3] == 0 && ei32[5] == 0 && ei32[7] == 0);
    int e = blockIdx.x * blockDim.x + threadIdx.x;
    if (e >= NE) return;
    if (is64) {
        const long long* e64 = (const long long*)ei32;
        SRC[e] = (int)e64[e];
        DST[e] = (int)e64[NE + e];
    } else {
        SRC[e] = ei32[e];
        DST[e] = ei32[NE + e];
    }
}

// ---------------- tf32 GEMM: 128(M) x 128(N) block, 256 threads (node side) -------
#define SA_STR 20
#define SB_STR 136
__global__ void __launch_bounds__(256) gemm_tf32(
    const float* __restrict__ A, const float* __restrict__ A2,
    const float* __restrict__ B, const float* __restrict__ bias,
    float* __restrict__ Cout, int M, int K, int Ncols,
    int reluFlag, const float* __restrict__ rowscale, const float* __restrict__ rowmask)
{
    __shared__ unsigned sA[128 * SA_STR];
    __shared__ unsigned sB[16 * SB_STR];
    const int bm = blockIdx.y * 128;
    const int bn = blockIdx.x * 128;
    const int tid = threadIdx.x;
    const int lane = tid & 31;
    const int warp = tid >> 5;
    const int wm = warp >> 1;   // 0..3
    const int wn = warp & 1;    // 0..1

    const int arow = tid >> 1;
    const int ac0  = (tid & 1) << 3;
    const int brow = tid >> 5;
    const int bn4  = (tid & 31) << 2;

    float acc[2][8][4];
#pragma unroll
    for (int i = 0; i < 2; i++)
#pragma unroll
        for (int j = 0; j < 8; j++)
#pragma unroll
            for (int q = 0; q < 4; q++) acc[i][j][q] = 0.f;

    uint4 pa0, pa1, pb0, pb1;
    {
        int grow = bm + arow;
        pa0 = make_uint4(0, 0, 0, 0); pa1 = make_uint4(0, 0, 0, 0);
        if (grow < M) {
            int gk = ac0;
            const float* s;
            if (A2) s = (gk < HH) ? (A + (long)grow * HH + gk) : (A2 + (long)grow * HH + gk - HH);
            else    s = A + (long)grow * K + gk;
            pa0 = *(const uint4*)s;
            pa1 = *(const uint4*)(s + 4);
        }
        pb0 = *(const uint4*)(B + (long)brow * Ncols + bn + bn4);
        pb1 = *(const uint4*)(B + (long)(brow + 8) * Ncols + bn + bn4);
    }

    for (int k0 = 0; k0 < K; k0 += 16) {
        *(uint4*)&sA[arow * SA_STR + ac0]     = pa0;
        *(uint4*)&sA[arow * SA_STR + ac0 + 4] = pa1;
        *(uint4*)&sB[brow * SB_STR + bn4]       = pb0;
        *(uint4*)&sB[(brow + 8) * SB_STR + bn4] = pb1;
        __syncthreads();

        int kn = k0 + 16;
        if (kn < K) {
            int grow = bm + arow;
            pa0 = make_uint4(0, 0, 0, 0); pa1 = make_uint4(0, 0, 0, 0);
            if (grow < M) {
                int gk = kn + ac0;
                const float* s;
                if (A2) s = (gk < HH) ? (A + (long)grow * HH + gk) : (A2 + (long)grow * HH + gk - HH);
                else    s = A + (long)grow * K + gk;
                pa0 = *(const uint4*)s;
                pa1 = *(const uint4*)(s + 4);
            }
            pb0 = *(const uint4*)(B + (long)(kn + brow) * Ncols + bn + bn4);
            pb1 = *(const uint4*)(B + (long)(kn + brow + 8) * Ncols + bn + bn4);
        }

#pragma unroll
        for (int ks = 0; ks < 2; ks++) {
            const int kk = ks * 8 + (lane & 3);
            unsigned a[2][4];
#pragma unroll
            for (int it = 0; it < 2; it++) {
                int rb = wm * 32 + it * 16 + (lane >> 2);
                a[it][0] = sA[rb * SA_STR + kk];
                a[it][1] = sA[(rb + 8) * SA_STR + kk];
                a[it][2] = sA[rb * SA_STR + kk + 4];
                a[it][3] = sA[(rb + 8) * SA_STR + kk + 4];
            }
#pragma unroll
            for (int jt = 0; jt < 8; jt++) {
                int nb = wn * 64 + jt * 8 + (lane >> 2);
                unsigned b0 = sB[kk * SB_STR + nb];
                unsigned b1 = sB[(kk + 4) * SB_STR + nb];
                mma8(acc[0][jt], a[0][0], a[0][1], a[0][2], a[0][3], b0, b1);
                mma8(acc[1][jt], a[1][0], a[1][1], a[1][2], a[1][3], b0, b1);
            }
        }
        __syncthreads();
    }

#pragma unroll
    for (int it = 0; it < 2; it++) {
        int row0 = bm + wm * 32 + it * 16 + (lane >> 2);
#pragma unroll
        for (int h = 0; h < 2; h++) {
            int row = row0 + h * 8;
            if (row >= M) continue;
            float rs = rowscale ? rowscale[row] : 1.f;
            float rm = rowmask ? rowmask[row] : 1.f;
#pragma unroll
            for (int jt = 0; jt < 8; jt++) {
                int col = bn + wn * 64 + jt * 8 + ((lane & 3) << 1);
                float v0 = acc[it][jt][h * 2 + 0] * rs;
                float v1 = acc[it][jt][h * 2 + 1] * rs;
                if (bias) { v0 += bias[col] * rm; v1 += bias[col + 1] * rm; }
                if (reluFlag) { v0 = fmaxf(v0, 0.f); v1 = fmaxf(v1, 0.f); }
                *(float2*)(Cout + (long)row * Ncols + col) = make_float2(v0, v1);
            }
        }
    }
}

// ---------------- FUSED edge kernel: 128 edges per block, double-buffered ----------
// phase 1 : H = relu(ea@W1c + b1 + U[dst] + V[src]) -> shared sH (ping-pong staging,
//           ONE sync per K-step)
// phase 1b: S[dst] += H (red.global.add.v4.f32, if doS)
// phase 2 : w = (relu(H@C + D)) . aW2 (16 steps over 2 column halves, ping-pong B,
//           ONE sync per step)
// tail    : equivariant pos accumulation into PACC
// Dynamic shared layout (bytes):
//  sH    @ 0      : 128*132*4 = 67584
//  sAe0  @ 67584  : 10240      sAe1 @ 77824 : 10240
//  sB1_0 @ 88064  : 8704       sB1_1 @ 96768 : 8704
//  sB2_0 overlays sAe0, sB2_1 overlays sAe1 (8704 <= 10240 each)
//  sDst @ 105472 (512), sSrc @ 105984 (512), red @ 106496 (1024) -> total 107520
#define SH_STR 132
#define FE_SMEM 107520
__global__ void __launch_bounds__(256) fused_edge(
    const float* __restrict__ EA, const float* __restrict__ W1c,
    const float* __restrict__ b1,
    const float* __restrict__ U, const float* __restrict__ V,
    const int* __restrict__ SRC, const int* __restrict__ DST,
    const float* __restrict__ Cm, const float* __restrict__ D,
    const float* __restrict__ aW2, const float* __restrict__ ab2,
    const float* __restrict__ POS,
    float* __restrict__ S, float* __restrict__ PACC, int doS)
{
    extern __shared__ char smem[];
    float*    sH   = (float*)smem;
    unsigned* sAeB[2] = { (unsigned*)(smem + 67584), (unsigned*)(smem + 77824) };
    unsigned* sB1B[2] = { (unsigned*)(smem + 88064), (unsigned*)(smem + 96768) };
    unsigned* sB2B[2] = { (unsigned*)(smem + 67584), (unsigned*)(smem + 77824) };
    int*   sDst = (int*)(smem + 105472);
    int*   sSrc = (int*)(smem + 105984);
    float (*red)[2] = (float(*)[2])(smem + 106496);

    const int bm = blockIdx.x * 128;
    const int tid = threadIdx.x;
    const int lane = tid & 31;
    const int warp = tid >> 5;
    const int wm = warp >> 1;   // 0..3
    const int wn = warp & 1;    // 0..1

    // stage edge indices (covered by the first phase-1 sync)
    if (tid < 128) {
        int e = bm + tid;
        sDst[tid] = (e < NE) ? DST[e] : 0;
        sSrc[tid] = (e < NE) ? SRC[e] : 0;
    }

    const int arow = tid >> 1;          // 0..127
    const int ac0  = (tid & 1) << 3;    // 0 or 8
    const int brow = tid >> 5;          // 0..7 (+8)
    const int bn4  = (tid & 31) << 2;   // 0..124

    // ---------------- phase 1: H = EA @ W1c (128 x 128, K=128), ping-pong ---------
    {
        float acc[2][8][4];
#pragma unroll
        for (int i = 0; i < 2; i++)
#pragma unroll
            for (int j = 0; j < 8; j++)
#pragma unroll
                for (int q = 0; q < 4; q++) acc[i][j][q] = 0.f;

        uint4 pa0, pa1, pb0, pb1;
        {
            int grow = bm + arow;
            pa0 = make_uint4(0, 0, 0, 0); pa1 = make_uint4(0, 0, 0, 0);
            if (grow < NE) {
                const float* s = EA + (long)grow * HH + ac0;
                pa0 = *(const uint4*)s;
                pa1 = *(const uint4*)(s + 4);
            }
            pb0 = *(const uint4*)(W1c + (long)brow * HH + bn4);
            pb1 = *(const uint4*)(W1c + (long)(brow + 8) * HH + bn4);
        }

        int b = 0;
#pragma unroll 1
        for (int k0 = 0; k0 < 128; k0 += 16) {
            unsigned* sAe = sAeB[b];
            unsigned* sB1 = sB1B[b];
            *(uint4*)&sAe[arow * SA_STR + ac0]     = pa0;
            *(uint4*)&sAe[arow * SA_STR + ac0 + 4] = pa1;
            *(uint4*)&sB1[brow * SB_STR + bn4]       = pb0;
            *(uint4*)&sB1[(brow + 8) * SB_STR + bn4] = pb1;
            __syncthreads();

            int kn = k0 + 16;
            if (kn < 128) {
                int grow = bm + arow;
                pa0 = make_uint4(0, 0, 0, 0); pa1 = make_uint4(0, 0, 0, 0);
                if (grow < NE) {
                    const float* s = EA + (long)grow * HH + kn + ac0;
                    pa0 = *(const uint4*)s;
                    pa1 = *(const uint4*)(s + 4);
                }
                pb0 = *(const uint4*)(W1c + (long)(kn + brow) * HH + bn4);
                pb1 = *(const uint4*)(W1c + (long)(kn + brow + 8) * HH + bn4);
            }

#pragma unroll
            for (int ks = 0; ks < 2; ks++) {
                const int kk = ks * 8 + (lane & 3);
                unsigned a[2][4];
#pragma unroll
                for (int it = 0; it < 2; it++) {
                    int rb = wm * 32 + it * 16 + (lane >> 2);
                    a[it][0] = sAe[rb * SA_STR + kk];
                    a[it][1] = sAe[(rb + 8) * SA_STR + kk];
                    a[it][2] = sAe[rb * SA_STR + kk + 4];
                    a[it][3] = sAe[(rb + 8) * SA_STR + kk + 4];
                }
#pragma unroll
                for (int jt = 0; jt < 8; jt++) {
                    int nb = wn * 64 + jt * 8 + (lane >> 2);
                    unsigned b0 = sB1[kk * SB_STR + nb];
                    unsigned b1r = sB1[(kk + 4) * SB_STR + nb];
                    mma8(acc[0][jt], a[0][0], a[0][1], a[0][2], a[0][3], b0, b1r);
                    mma8(acc[1][jt], a[1][0], a[1][1], a[1][2], a[1][3], b0, b1r);
                }
            }
            b ^= 1;
        }

        // epilogue: + b1 + U[dst] + V[src], relu, -> sH
#pragma unroll
        for (int it = 0; it < 2; it++) {
#pragma unroll
            for (int h = 0; h < 2; h++) {
                int r = wm * 32 + it * 16 + (lane >> 2) + h * 8;
                bool valid = (bm + r) < NE;
                int d = sDst[r], s = sSrc[r];
#pragma unroll
                for (int jt = 0; jt < 8; jt++) {
                    int c = wn * 64 + jt * 8 + ((lane & 3) << 1);
                    float v0 = 0.f, v1 = 0.f;
                    if (valid) {
                        float2 uu = *(const float2*)(U + (long)d * HH + c);
                        float2 vv = *(const float2*)(V + (long)s * HH + c);
                        v0 = fmaxf(acc[it][jt][h * 2 + 0] + b1[c]     + uu.x + vv.x, 0.f);
                        v1 = fmaxf(acc[it][jt][h * 2 + 1] + b1[c + 1] + uu.y + vv.y, 0.f);
                    }
                    *(float2*)&sH[r * SH_STR + c] = make_float2(v0, v1);
                }
            }
        }
    }
    __syncthreads();   // sH complete; also: all phase-1 computes done before sB2 overlay

    // ---------------- phase 1b: S[dst] += H (vector red) ----------------
    if (doS) {
        int r = tid >> 1;
        int cb = (tid & 1) << 6;   // 0 or 64
        if (bm + r < NE) {
            float* base = S + (long)sDst[r] * HH + cb;
            const float* hrow = sH + r * SH_STR + cb;
#pragma unroll
            for (int p = 0; p < 16; p++) {
                float4 v = *(const float4*)(hrow + p * 4);
                if (v.x != 0.f || v.y != 0.f || v.z != 0.f || v.w != 0.f) {
                    asm volatile("red.global.add.v4.f32 [%0], {%1,%2,%3,%4};"
                                 :: "l"(base + p * 4), "f"(v.x), "f"(v.y), "f"(v.z), "f"(v.w)
                                 : "memory");
                }
            }
        }
    }

    // ---------------- phase 2: w = (relu(H@C + D)) . aW2, 16 ping-pong steps ------
    float ws[2][2];
    ws[0][0] = ws[0][1] = ws[1][0] = ws[1][1] = 0.f;
    {
        float acc2[2][8][4];
        uint4 pb0 = *(const uint4*)(Cm + (long)brow * 256 + bn4);
        uint4 pb1 = *(const uint4*)(Cm + (long)(brow + 8) * 256 + bn4);
        int b = 0;

#pragma unroll 1
        for (int step = 0; step < 16; step++) {
            const int ch = step >> 3;
            const int k0 = (step & 7) << 4;
            if ((step & 7) == 0) {
#pragma unroll
                for (int i = 0; i < 2; i++)
#pragma unroll
                    for (int j = 0; j < 8; j++)
#pragma unroll
                        for (int q = 0; q < 4; q++) acc2[i][j][q] = 0.f;
            }

            unsigned* sB2 = sB2B[b];
            *(uint4*)&sB2[brow * SB_STR + bn4]       = pb0;
            *(uint4*)&sB2[(brow + 8) * SB_STR + bn4] = pb1;
            __syncthreads();

            int ns = step + 1;
            if (ns < 16) {
                int nch = ns >> 3, nk = (ns & 7) << 4;
                pb0 = *(const uint4*)(Cm + (long)(nk + brow) * 256 + nch * 128 + bn4);
                pb1 = *(const uint4*)(Cm + (long)(nk + brow + 8) * 256 + nch * 128 + bn4);
            }

#pragma unroll
            for (int ks = 0; ks < 2; ks++) {
                const int kkl = ks * 8 + (lane & 3);
                const int kkg = k0 + kkl;
                unsigned a[2][4];
#pragma unroll
                for (int it = 0; it < 2; it++) {
                    int rb = wm * 32 + it * 16 + (lane >> 2);
                    a[it][0] = __float_as_uint(sH[rb * SH_STR + kkg]);
                    a[it][1] = __float_as_uint(sH[(rb + 8) * SH_STR + kkg]);
                    a[it][2] = __float_as_uint(sH[rb * SH_STR + kkg + 4]);
                    a[it][3] = __float_as_uint(sH[(rb + 8) * SH_STR + kkg + 4]);
                }
#pragma unroll
                for (int jt = 0; jt < 8; jt++) {
                    int nb = wn * 64 + jt * 8 + (lane >> 2);
                    unsigned b0 = sB2[kkl * SB_STR + nb];
                    unsigned b1r = sB2[(kkl + 4) * SB_STR + nb];
                    mma8(acc2[0][jt], a[0][0], a[0][1], a[0][2], a[0][3], b0, b1r);
                    mma8(acc2[1][jt], a[1][0], a[1][1], a[1][2], a[1][3], b0, b1r);
                }
            }

            if ((step & 7) == 7) {
                // fold this half into per-row partial dots
#pragma unroll
                for (int it = 0; it < 2; it++) {
#pragma unroll
                    for (int jt = 0; jt < 8; jt++) {
                        int col = ch * 128 + wn * 64 + jt * 8 + ((lane & 3) << 1);
                        float d0 = D[col], d1 = D[col + 1];
                        float w0 = aW2[col], w1 = aW2[col + 1];
                        ws[it][0] += fmaxf(acc2[it][jt][0] + d0, 0.f) * w0
                                   + fmaxf(acc2[it][jt][1] + d1, 0.f) * w1;
                        ws[it][1] += fmaxf(acc2[it][jt][2] + d0, 0.f) * w0
                                   + fmaxf(acc2[it][jt][3] + d1, 0.f) * w1;
                    }
                }
            }
            b ^= 1;
        }
    }

    // cross-lane reduce (over lane&3) and stage per-row partials
#pragma unroll
    for (int it = 0; it < 2; it++) {
#pragma unroll
        for (int h = 0; h < 2; h++) {
            float s = ws[it][h];
            s += __shfl_xor_sync(0xffffffffu, s, 1);
            s += __shfl_xor_sync(0xffffffffu, s, 2);
            if ((lane & 3) == 0) {
                int r = wm * 32 + it * 16 + (lane >> 2) + h * 8;
                red[r][wn] = s;
            }
        }
    }
    __syncthreads();

    // tail: fused equivariant pos accumulation
    if (tid < 128) {
        int e = bm + tid;
        if (e < NE) {
            float w = red[tid][0] + red[tid][1] + ab2[0];
            int src = sSrc[tid], dst = sDst[tid];
            float rx = POS[src * 3 + 0] - POS[dst * 3 + 0];
            float ry = POS[src * 3 + 1] - POS[dst * 3 + 1];
            float rz = POS[src * 3 + 2] - POS[dst * 3 + 2];
            float dist = sqrtf(rx * rx + ry * ry + rz * rz);
            float sc = w / dist;
            atomicAdd(&PACC[dst * 3 + 0], sc * rx);
            atomicAdd(&PACC[dst * 3 + 1], sc * ry);
            atomicAdd(&PACC[dst * 3 + 2], sc * rz);
        }
    }
}

// ---------------- small per-layer prep: C = W2@aW1, D = b2@aW1 + ab1 --------------
__global__ void prep_kernel(const float* __restrict__ W2, const float* __restrict__ aW1,
                            const float* __restrict__ b2, const float* __restrict__ ab1,
                            float* __restrict__ C, float* __restrict__ D)
{
    int j = threadIdx.x;   // 0..255
    int k = blockIdx.x;    // 0..128
    if (k < 128) {
        float s = 0.f;
#pragma unroll 8
        for (int t = 0; t < 128; t++) s += W2[k * 128 + t] * aW1[t * 256 + j];
        C[k * 256 + j] = s;
    } else {
        float s = ab1[j];
#pragma unroll 8
        for (int t = 0; t < 128; t++) s += b2[t] * aW1[t * 256 + j];
        D[j] = s;
    }
}

// ---------------- degree / denom -------------------------------------------------
__global__ void deg_kernel(const int* __restrict__ DST, float* __restrict__ DEG)
{
    int e = blockIdx.x * blockDim.x + threadIdx.x;
    if (e < NE) atomicAdd(&DEG[DST[e]], 1.f);
}

__global__ void dinv_kernel(const float* __restrict__ DEG, float* __restrict__ DINV,
                            float* __restrict__ BM)
{
    int n = blockIdx.x * blockDim.x + threadIdx.x;
    if (n >= NN) return;
    float d = DEG[n];
    DINV[n] = 1.f / fmaxf(d, 1.f);
    BM[n] = (d > 0.f) ? 1.f : 0.f;
}

__global__ void pos_apply_kernel(float* __restrict__ POS, const float* __restrict__ PACC,
                                 const float* __restrict__ DINV, float* __restrict__ outp)
{
    int n = blockIdx.x * blockDim.x + threadIdx.x;
    if (n >= NN) return;
    float di = DINV[n];
#pragma unroll
    for (int i = 0; i < 3; i++) {
        float v = POS[n * 3 + i] + PACC[n * 3 + i] * di;
        POS[n * 3 + i] = v;
        if (outp) outp[n * 3 + i] = v;
    }
}

// ---------------- host ------------------------------------------------------------
extern "C" void kernel_launch(void* const* d_in, const int* in_sizes, int n_in,
                              void* d_out, int out_size)
{
    const float* x        = (const float*)d_in[0];
    const int*   ei32     = (const int*)d_in[1];
    const float* ea       = (const float*)d_in[2];
    const float* pos      = (const float*)d_in[3];
    const float* mW1      = (const float*)d_in[4];
    const float* mb1      = (const float*)d_in[5];
    const float* mW2      = (const float*)d_in[6];
    const float* mb2      = (const float*)d_in[7];
    const float* aW1      = (const float*)d_in[8];
    const float* ab1      = (const float*)d_in[9];
    const float* aW2      = (const float*)d_in[10];
    const float* ab2      = (const float*)d_in[11];
    const float* nW1      = (const float*)d_in[12];
    const float* nb1      = (const float*)d_in[13];
    const float* nW2      = (const float*)d_in[14];
    const float* nb2      = (const float*)d_in[15];
    float* outp = (float*)d_out;

    float *pU, *pV, *pS, *pINTRA, *pHID, *pXA, *pXB, *pPOS, *pPACC;
    float *pDEG, *pDINV, *pBM, *pC, *pD;
    int *pSRC, *pDST;
    cudaGetSymbolAddress((void**)&pU, g_U);
    cudaGetSymbolAddress((void**)&pV, g_V);
    cudaGetSymbolAddress((void**)&pS, g_S);
    cudaGetSymbolAddress((void**)&pINTRA, g_INTRA);
    cudaGetSymbolAddress((void**)&pHID, g_HID);
    cudaGetSymbolAddress((void**)&pXA, g_XA);
    cudaGetSymbolAddress((void**)&pXB, g_XB);
    cudaGetSymbolAddress((void**)&pPOS, g_POS);
    cudaGetSymbolAddress((void**)&pPACC, g_POSACC);
    cudaGetSymbolAddress((void**)&pDEG, g_DEG);
    cudaGetSymbolAddress((void**)&pDINV, g_DINV);
    cudaGetSymbolAddress((void**)&pBM, g_BMASK);
    cudaGetSymbolAddress((void**)&pC, g_C);
    cudaGetSymbolAddress((void**)&pD, g_D);
    cudaGetSymbolAddress((void**)&pSRC, g_SRC);
    cudaGetSymbolAddress((void**)&pDST, g_DST);

    static int attr_done = 0;
    if (!attr_done) {
        cudaFuncSetAttribute(fused_edge, cudaFuncAttributeMaxDynamicSharedMemorySize, FE_SMEM);
        attr_done = 1;
    }

    cudaMemcpyAsync(pPOS, pos, (size_t)NN * 3 * sizeof(float), cudaMemcpyDeviceToDevice);
    convert_idx<<<(NE + 255) / 256, 256>>>(ei32, pSRC, pDST);
    cudaMemsetAsync(pDEG, 0, (size_t)NN * sizeof(float));
    deg_kernel<<<(NE + 255) / 256, 256>>>(pDST, pDEG);
    dinv_kernel<<<(NN + 255) / 256, 256>>>(pDEG, pDINV, pBM);

    const float* xc = x;
    float* xn = pXA;

    for (int l = 0; l < 3; l++) {
        const int last = (l == 2);
        const float* mW1l = mW1 + (long)l * 384 * 128;
        const float* mb1l = mb1 + (long)l * 128;
        const float* mW2l = mW2 + (long)l * 128 * 128;
        const float* mb2l = mb2 + (long)l * 128;
        const float* aW1l = aW1 + (long)l * 128 * 256;
        const float* ab1l = ab1 + (long)l * 256;
        const float* aW2l = aW2 + (long)l * 256;
        const float* ab2l = ab2 + (long)l;
        const float* nW1l = nW1 + (long)l * 256 * 256;
        const float* nb1l = nb1 + (long)l * 256;
        const float* nW2l = nW2 + (long)l * 256 * 128;
        const float* nb2l = nb2 + (long)l * 128;

        if (!last) cudaMemsetAsync(pS, 0, (size_t)NN * HH * sizeof(float));
        cudaMemsetAsync(pPACC, 0, (size_t)NN * 3 * sizeof(float));

        prep_kernel<<<129, 256>>>(mW2l, aW1l, mb2l, ab1l, pC, pD);

        dim3 gN(1, (NN + 127) / 128);
        gemm_tf32<<<gN, 256>>>(xc, nullptr, mW1l, nullptr, pU, NN, 128, 128, 0, nullptr, nullptr);
        gemm_tf32<<<gN, 256>>>(xc, nullptr, mW1l + 128 * 128, nullptr, pV, NN, 128, 128, 0, nullptr, nullptr);

        fused_edge<<<(NE + 127) / 128, 256, FE_SMEM>>>(
            ea, mW1l + 256 * 128, mb1l, pU, pV, pSRC, pDST,
            pC, pD, aW2l, ab2l, pPOS, pS, pPACC, last ? 0 : 1);

        pos_apply_kernel<<<(NN + 255) / 256, 256>>>(pPOS, pPACC, pDINV, last ? outp : nullptr);

        if (!last) {
            gemm_tf32<<<gN, 256>>>(pS, nullptr, mW2l, mb2l, pINTRA, NN, 128, 128, 0, pDINV, pBM);
            dim3 gH(2, (NN + 127) / 128);
            gemm_tf32<<<gH, 256>>>(xc, pINTRA, nW1l, nb1l, pHID, NN, 256, 256, 1, nullptr, nullptr);
            gemm_tf32<<<gN, 256>>>(pHID, nullptr, nW2l, nb2l, xn, NN, 256, 128, 0, nullptr, nullptr);
            xc = xn;
            xn = (xn == pXA) ? pXB : pXA;
        }
    }
}

// round 14
// speedup vs baseline: 1.3533x; 1.3533x over previous
#include <cuda_runtime.h>
#include <cstdint>

#define NN 50000
#define NE 500000
#define HH 128

// ---------------- scratch (device globals; no cudaMalloc allowed) ----------------
__device__ float g_U[NN * HH];
__device__ float g_V[NN * HH];
__device__ float g_S[NN * HH];          // segment sum of relu(h)
__device__ float g_INTRA[NN * HH];
__device__ float g_HID[NN * 2 * HH];
__device__ float g_XA[NN * HH];
__device__ float g_XB[NN * HH];
__device__ float g_POS[NN * 3];
__device__ float g_POSACC[NN * 3];
__device__ float g_DEG[NN];
__device__ float g_DINV[NN];
__device__ float g_BMASK[NN];
__device__ float g_C[HH * 256];         // W2 @ aW1 (fp32)
__device__ unsigned g_CB[64 * 256];     // C packed bf16x2 along k: word[kp][n] = {lo=C[2kp][n], hi=C[2kp+1][n]}
__device__ float g_D[256];              // b2 @ aW1 + ab1
__device__ int   g_SRC[NE];
__device__ int   g_DST[NE];

// ---------------- mma helpers ------------------------------------------------------
__device__ __forceinline__ void mma8(float c[4],
                                     unsigned a0, unsigned a1, unsigned a2, unsigned a3,
                                     unsigned b0, unsigned b1) {
    asm("mma.sync.aligned.m16n8k8.row.col.f32.tf32.tf32.f32 "
        "{%0,%1,%2,%3},{%4,%5,%6,%7},{%8,%9},{%0,%1,%2,%3};"
        : "+f"(c[0]), "+f"(c[1]), "+f"(c[2]), "+f"(c[3])
        : "r"(a0), "r"(a1), "r"(a2), "r"(a3), "r"(b0), "r"(b1));
}

__device__ __forceinline__ void mma16(float c[4],
                                      unsigned a0, unsigned a1, unsigned a2, unsigned a3,
                                      unsigned b0, unsigned b1) {
    asm("mma.sync.aligned.m16n8k16.row.col.f32.bf16.bf16.f32 "
        "{%0,%1,%2,%3},{%4,%5,%6,%7},{%8,%9},{%0,%1,%2,%3};"
        : "+f"(c[0]), "+f"(c[1]), "+f"(c[2]), "+f"(c[3])
        : "r"(a0), "r"(a1), "r"(a2), "r"(a3), "r"(b0), "r"(b1));
}

__device__ __forceinline__ unsigned pack_bf16x2(float lo, float hi) {
    unsigned w;
    asm("cvt.rn.bf16x2.f32 %0, %1, %2;" : "=r"(w) : "f"(hi), "f"(lo));
    return w;
}

// -------- index normalization: handles harness storing edge_index as int32 OR int64
__global__ void convert_idx(const int* __restrict__ ei32, int* __restrict__ SRC,
                            int* __restrict__ DST)
{
    bool is64 = (ei32[1] == 0 && ei32[3] == 0 && ei32[5] == 0 && ei32[7] == 0);
    int e = blockIdx.x * blockDim.x + threadIdx.x;
    if (e >= NE) return;
    if (is64) {
        const long long* e64 = (const long long*)ei32;
        SRC[e] = (int)e64[e];
        DST[e] = (int)e64[NE + e];
    } else {
        SRC[e] = ei32[e];
        DST[e] = ei32[NE + e];
    }
}

// ---------------- tf32 GEMM: 128(M) x 128(N) block, 256 threads (node side) -------
#define SA_STR 20
#define SB_STR 136
__global__ void __launch_bounds__(256) gemm_tf32(
    const float* __restrict__ A, const float* __restrict__ A2,
    const float* __restrict__ B, const float* __restrict__ bias,
    float* __restrict__ Cout, int M, int K, int Ncols,
    int reluFlag, const float* __restrict__ rowscale, const float* __restrict__ rowmask)
{
    __shared__ unsigned sA[128 * SA_STR];
    __shared__ unsigned sB[16 * SB_STR];
    const int bm = blockIdx.y * 128;
    const int bn = blockIdx.x * 128;
    const int tid = threadIdx.x;
    const int lane = tid & 31;
    const int warp = tid >> 5;
    const int wm = warp >> 1;   // 0..3
    const int wn = warp & 1;    // 0..1

    const int arow = tid >> 1;
    const int ac0  = (tid & 1) << 3;
    const int brow = tid >> 5;
    const int bn4  = (tid & 31) << 2;

    float acc[2][8][4];
#pragma unroll
    for (int i = 0; i < 2; i++)
#pragma unroll
        for (int j = 0; j < 8; j++)
#pragma unroll
            for (int q = 0; q < 4; q++) acc[i][j][q] = 0.f;

    uint4 pa0, pa1, pb0, pb1;
    {
        int grow = bm + arow;
        pa0 = make_uint4(0, 0, 0, 0); pa1 = make_uint4(0, 0, 0, 0);
        if (grow < M) {
            int gk = ac0;
            const float* s;
            if (A2) s = (gk < HH) ? (A + (long)grow * HH + gk) : (A2 + (long)grow * HH + gk - HH);
            else    s = A + (long)grow * K + gk;
            pa0 = *(const uint4*)s;
            pa1 = *(const uint4*)(s + 4);
        }
        pb0 = *(const uint4*)(B + (long)brow * Ncols + bn + bn4);
        pb1 = *(const uint4*)(B + (long)(brow + 8) * Ncols + bn + bn4);
    }

    for (int k0 = 0; k0 < K; k0 += 16) {
        *(uint4*)&sA[arow * SA_STR + ac0]     = pa0;
        *(uint4*)&sA[arow * SA_STR + ac0 + 4] = pa1;
        *(uint4*)&sB[brow * SB_STR + bn4]       = pb0;
        *(uint4*)&sB[(brow + 8) * SB_STR + bn4] = pb1;
        __syncthreads();

        int kn = k0 + 16;
        if (kn < K) {
            int grow = bm + arow;
            pa0 = make_uint4(0, 0, 0, 0); pa1 = make_uint4(0, 0, 0, 0);
            if (grow < M) {
                int gk = kn + ac0;
                const float* s;
                if (A2) s = (gk < HH) ? (A + (long)grow * HH + gk) : (A2 + (long)grow * HH + gk - HH);
                else    s = A + (long)grow * K + gk;
                pa0 = *(const uint4*)s;
                pa1 = *(const uint4*)(s + 4);
            }
            pb0 = *(const uint4*)(B + (long)(kn + brow) * Ncols + bn + bn4);
            pb1 = *(const uint4*)(B + (long)(kn + brow + 8) * Ncols + bn + bn4);
        }

#pragma unroll
        for (int ks = 0; ks < 2; ks++) {
            const int kk = ks * 8 + (lane & 3);
            unsigned a[2][4];
#pragma unroll
            for (int it = 0; it < 2; it++) {
                int rb = wm * 32 + it * 16 + (lane >> 2);
                a[it][0] = sA[rb * SA_STR + kk];
                a[it][1] = sA[(rb + 8) * SA_STR + kk];
                a[it][2] = sA[rb * SA_STR + kk + 4];
                a[it][3] = sA[(rb + 8) * SA_STR + kk + 4];
            }
#pragma unroll
            for (int jt = 0; jt < 8; jt++) {
                int nb = wn * 64 + jt * 8 + (lane >> 2);
                unsigned b0 = sB[kk * SB_STR + nb];
                unsigned b1 = sB[(kk + 4) * SB_STR + nb];
                mma8(acc[0][jt], a[0][0], a[0][1], a[0][2], a[0][3], b0, b1);
                mma8(acc[1][jt], a[1][0], a[1][1], a[1][2], a[1][3], b0, b1);
            }
        }
        __syncthreads();
    }

#pragma unroll
    for (int it = 0; it < 2; it++) {
        int row0 = bm + wm * 32 + it * 16 + (lane >> 2);
#pragma unroll
        for (int h = 0; h < 2; h++) {
            int row = row0 + h * 8;
            if (row >= M) continue;
            float rs = rowscale ? rowscale[row] : 1.f;
            float rm = rowmask ? rowmask[row] : 1.f;
#pragma unroll
            for (int jt = 0; jt < 8; jt++) {
                int col = bn + wn * 64 + jt * 8 + ((lane & 3) << 1);
                float v0 = acc[it][jt][h * 2 + 0] * rs;
                float v1 = acc[it][jt][h * 2 + 1] * rs;
                if (bias) { v0 += bias[col] * rm; v1 += bias[col + 1] * rm; }
                if (reluFlag) { v0 = fmaxf(v0, 0.f); v1 = fmaxf(v1, 0.f); }
                *(float2*)(Cout + (long)row * Ncols + col) = make_float2(v0, v1);
            }
        }
    }
}

// ---------------- FUSED edge kernel: 128 edges per block ---------------------------
// phase 1 : H = relu(ea@W1c + b1 + U[dst] + V[src])  (tf32, R11 structure)
//           -> stored as packed bf16x2 in sHb
// phase 1b: S[dst] += H (unpack bf16, red.global.add.v4.f32, if doS)
// phase 2 : w = (relu(H@C + D)) . aW2 -- bf16 m16n8k16, 8 staged steps from g_CB
// tail    : equivariant pos accumulation into PACC
// Dynamic shared layout (bytes):
//  sHb  @ 0     : 128*68*4 = 34816   (bf16x2 words; stride 68 %32==4 -> A frags CF)
//  sAe  @ 34816 : 10240   (phase-1 A staging)
//  sB1  @ 45056 : 8704    (phase-1 B staging; region end 53760)
//  sB2 overlays sAe @ 34816 : 16*136*4 = 8704 (phase-2 B; stride %32==8 CF)
//  sDst @ 53760 (512), sSrc @ 54272 (512), red @ 54784 (1024) -> total 55808
#define SHB_STR 68
#define FE_SMEM 55808
__global__ void __launch_bounds__(256) fused_edge(
    const float* __restrict__ EA, const float* __restrict__ W1c,
    const float* __restrict__ b1,
    const float* __restrict__ U, const float* __restrict__ V,
    const int* __restrict__ SRC, const int* __restrict__ DST,
    const unsigned* __restrict__ CB, const float* __restrict__ D,
    const float* __restrict__ aW2, const float* __restrict__ ab2,
    const float* __restrict__ POS,
    float* __restrict__ S, float* __restrict__ PACC, int doS)
{
    extern __shared__ char smem[];
    unsigned* sHb = (unsigned*)smem;
    unsigned* sAe = (unsigned*)(smem + 34816);
    unsigned* sB1 = (unsigned*)(smem + 45056);
    unsigned* sB2 = (unsigned*)(smem + 34816);
    int*   sDst = (int*)(smem + 53760);
    int*   sSrc = (int*)(smem + 54272);
    float (*red)[2] = (float(*)[2])(smem + 54784);

    const int bm = blockIdx.x * 128;
    const int tid = threadIdx.x;
    const int lane = tid & 31;
    const int warp = tid >> 5;
    const int wm = warp >> 1;   // 0..3
    const int wn = warp & 1;    // 0..1

    // stage edge indices (covered by first phase-1 sync)
    if (tid < 128) {
        int e = bm + tid;
        sDst[tid] = (e < NE) ? DST[e] : 0;
        sSrc[tid] = (e < NE) ? SRC[e] : 0;
    }

    const int arow = tid >> 1;          // 0..127
    const int ac0  = (tid & 1) << 3;    // 0 or 8
    const int brow = tid >> 5;          // 0..7 (+8)
    const int bn4  = (tid & 31) << 2;   // 0..124

    // ---------------- phase 1: H = EA @ W1c (128 x 128, K=128), tf32 ---------------
    {
        float acc[2][8][4];
#pragma unroll
        for (int i = 0; i < 2; i++)
#pragma unroll
            for (int j = 0; j < 8; j++)
#pragma unroll
                for (int q = 0; q < 4; q++) acc[i][j][q] = 0.f;

        uint4 pa0, pa1, pb0, pb1;
        {
            int grow = bm + arow;
            pa0 = make_uint4(0, 0, 0, 0); pa1 = make_uint4(0, 0, 0, 0);
            if (grow < NE) {
                const float* s = EA + (long)grow * HH + ac0;
                pa0 = *(const uint4*)s;
                pa1 = *(const uint4*)(s + 4);
            }
            pb0 = *(const uint4*)(W1c + (long)brow * HH + bn4);
            pb1 = *(const uint4*)(W1c + (long)(brow + 8) * HH + bn4);
        }

        for (int k0 = 0; k0 < 128; k0 += 16) {
            *(uint4*)&sAe[arow * SA_STR + ac0]     = pa0;
            *(uint4*)&sAe[arow * SA_STR + ac0 + 4] = pa1;
            *(uint4*)&sB1[brow * SB_STR + bn4]       = pb0;
            *(uint4*)&sB1[(brow + 8) * SB_STR + bn4] = pb1;
            __syncthreads();

            int kn = k0 + 16;
            if (kn < 128) {
                int grow = bm + arow;
                pa0 = make_uint4(0, 0, 0, 0); pa1 = make_uint4(0, 0, 0, 0);
                if (grow < NE) {
                    const float* s = EA + (long)grow * HH + kn + ac0;
                    pa0 = *(const uint4*)s;
                    pa1 = *(const uint4*)(s + 4);
                }
                pb0 = *(const uint4*)(W1c + (long)(kn + brow) * HH + bn4);
                pb1 = *(const uint4*)(W1c + (long)(kn + brow + 8) * HH + bn4);
            }

#pragma unroll
            for (int ks = 0; ks < 2; ks++) {
                const int kk = ks * 8 + (lane & 3);
                unsigned a[2][4];
#pragma unroll
                for (int it = 0; it < 2; it++) {
                    int rb = wm * 32 + it * 16 + (lane >> 2);
                    a[it][0] = sAe[rb * SA_STR + kk];
                    a[it][1] = sAe[(rb + 8) * SA_STR + kk];
                    a[it][2] = sAe[rb * SA_STR + kk + 4];
                    a[it][3] = sAe[(rb + 8) * SA_STR + kk + 4];
                }
#pragma unroll
                for (int jt = 0; jt < 8; jt++) {
                    int nb = wn * 64 + jt * 8 + (lane >> 2);
                    unsigned b0 = sB1[kk * SB_STR + nb];
                    unsigned b1r = sB1[(kk + 4) * SB_STR + nb];
                    mma8(acc[0][jt], a[0][0], a[0][1], a[0][2], a[0][3], b0, b1r);
                    mma8(acc[1][jt], a[1][0], a[1][1], a[1][2], a[1][3], b0, b1r);
                }
            }
            __syncthreads();
        }

        // epilogue: + b1 + U[dst] + V[src], relu, pack bf16x2 -> sHb
#pragma unroll
        for (int it = 0; it < 2; it++) {
#pragma unroll
            for (int h = 0; h < 2; h++) {
                int r = wm * 32 + it * 16 + (lane >> 2) + h * 8;
                bool valid = (bm + r) < NE;
                int d = sDst[r], s = sSrc[r];
#pragma unroll
                for (int jt = 0; jt < 8; jt++) {
                    int c = wn * 64 + jt * 8 + ((lane & 3) << 1);
                    float v0 = 0.f, v1 = 0.f;
                    if (valid) {
                        float2 uu = *(const float2*)(U + (long)d * HH + c);
                        float2 vv = *(const float2*)(V + (long)s * HH + c);
                        v0 = fmaxf(acc[it][jt][h * 2 + 0] + b1[c]     + uu.x + vv.x, 0.f);
                        v1 = fmaxf(acc[it][jt][h * 2 + 1] + b1[c + 1] + uu.y + vv.y, 0.f);
                    }
                    sHb[r * SHB_STR + (c >> 1)] = pack_bf16x2(v0, v1);
                }
            }
        }
    }
    __syncthreads();   // sHb complete; all phase-1 shared reads done before sB2 overlay

    // ---------------- phase 1b: S[dst] += H (unpack bf16, vector red) --------------
    if (doS) {
        int r = tid >> 1;
        int wb = (tid & 1) << 5;   // word base 0 or 32 (cols 0 or 64)
        if (bm + r < NE) {
            float* base = S + (long)sDst[r] * HH + (wb << 1);
            const unsigned* hrow = sHb + r * SHB_STR + wb;
#pragma unroll
            for (int p = 0; p < 16; p++) {
                unsigned w0 = hrow[p * 2], w1 = hrow[p * 2 + 1];
                if (w0 | w1) {
                    float f0 = __uint_as_float(w0 << 16);
                    float f1 = __uint_as_float(w0 & 0xffff0000u);
                    float f2 = __uint_as_float(w1 << 16);
                    float f3 = __uint_as_float(w1 & 0xffff0000u);
                    asm volatile("red.global.add.v4.f32 [%0], {%1,%2,%3,%4};"
                                 :: "l"(base + p * 4), "f"(f0), "f"(f1), "f"(f2), "f"(f3)
                                 : "memory");
                }
            }
        }
    }

    // ---------------- phase 2: w = (relu(H@C + D)) . aW2, bf16 m16n8k16 -----------
    float ws[2][2];
    ws[0][0] = ws[0][1] = ws[1][0] = ws[1][1] = 0.f;
    {
        const int kprow = tid >> 4;         // 0..15
        const int nb8 = (tid & 15) << 3;    // 0..120
        float acc2[2][8][4];
        uint4 pc0 = *(const uint4*)(CB + kprow * 256 + nb8);
        uint4 pc1 = *(const uint4*)(CB + kprow * 256 + nb8 + 4);

#pragma unroll 1
        for (int step = 0; step < 8; step++) {
            const int ch = step >> 2;       // column half 0/1
            const int sc = step & 3;        // k super-chunk (32 k each)
            if (sc == 0) {
#pragma unroll
                for (int i = 0; i < 2; i++)
#pragma unroll
                    for (int j = 0; j < 8; j++)
#pragma unroll
                        for (int q = 0; q < 4; q++) acc2[i][j][q] = 0.f;
            }

            __syncthreads();   // previous step's sB2 reads complete (first: harmless)
            *(uint4*)&sB2[kprow * SB_STR + nb8]     = pc0;
            *(uint4*)&sB2[kprow * SB_STR + nb8 + 4] = pc1;
            __syncthreads();

            int ns = step + 1;
            if (ns < 8) {
                int nch = ns >> 2, nsc = ns & 3;
                const unsigned* src = CB + (nsc * 16 + kprow) * 256 + nch * 128 + nb8;
                pc0 = *(const uint4*)src;
                pc1 = *(const uint4*)(src + 4);
            }

#pragma unroll
            for (int q = 0; q < 2; q++) {
                const int awb = sc * 16 + q * 8 + (lane & 3);   // A word index base
                unsigned a[2][4];
#pragma unroll
                for (int it = 0; it < 2; it++) {
                    int rb = wm * 32 + it * 16 + (lane >> 2);
                    a[it][0] = sHb[rb * SHB_STR + awb];
                    a[it][1] = sHb[(rb + 8) * SHB_STR + awb];
                    a[it][2] = sHb[rb * SHB_STR + awb + 4];
                    a[it][3] = sHb[(rb + 8) * SHB_STR + awb + 4];
                }
                const int kpl = q * 8 + (lane & 3);
#pragma unroll
                for (int jt = 0; jt < 8; jt++) {
                    int nb = wn * 64 + jt * 8 + (lane >> 2);
                    unsigned b0 = sB2[kpl * SB_STR + nb];
                    unsigned b1r = sB2[(kpl + 4) * SB_STR + nb];
                    mma16(acc2[0][jt], a[0][0], a[0][1], a[0][2], a[0][3], b0, b1r);
                    mma16(acc2[1][jt], a[1][0], a[1][1], a[1][2], a[1][3], b0, b1r);
                }
            }

            if (sc == 3) {
                // fold this half into per-row partial dots
#pragma unroll
                for (int it = 0; it < 2; it++) {
#pragma unroll
                    for (int jt = 0; jt < 8; jt++) {
                        int col = ch * 128 + wn * 64 + jt * 8 + ((lane & 3) << 1);
                        float d0 = D[col], d1 = D[col + 1];
                        float w0 = aW2[col], w1 = aW2[col + 1];
                        ws[it][0] += fmaxf(acc2[it][jt][0] + d0, 0.f) * w0
                                   + fmaxf(acc2[it][jt][1] + d1, 0.f) * w1;
                        ws[it][1] += fmaxf(acc2[it][jt][2] + d0, 0.f) * w0
                                   + fmaxf(acc2[it][jt][3] + d1, 0.f) * w1;
                    }
                }
            }
        }
    }

    // cross-lane reduce (over lane&3) and stage per-row partials
#pragma unroll
    for (int it = 0; it < 2; it++) {
#pragma unroll
        for (int h = 0; h < 2; h++) {
            float s = ws[it][h];
            s += __shfl_xor_sync(0xffffffffu, s, 1);
            s += __shfl_xor_sync(0xffffffffu, s, 2);
            if ((lane & 3) == 0) {
                int r = wm * 32 + it * 16 + (lane >> 2) + h * 8;
                red[r][wn] = s;
            }
        }
    }
    __syncthreads();

    // tail: fused equivariant pos accumulation
    if (tid < 128) {
        int e = bm + tid;
        if (e < NE) {
            float w = red[tid][0] + red[tid][1] + ab2[0];
            int src = sSrc[tid], dst = sDst[tid];
            float rx = POS[src * 3 + 0] - POS[dst * 3 + 0];
            float ry = POS[src * 3 + 1] - POS[dst * 3 + 1];
            float rz = POS[src * 3 + 2] - POS[dst * 3 + 2];
            float dist = sqrtf(rx * rx + ry * ry + rz * rz);
            float sc = w / dist;
            atomicAdd(&PACC[dst * 3 + 0], sc * rx);
            atomicAdd(&PACC[dst * 3 + 1], sc * ry);
            atomicAdd(&PACC[dst * 3 + 2], sc * rz);
        }
    }
}

// ---------------- small per-layer prep: C = W2@aW1, D = b2@aW1 + ab1 --------------
__global__ void prep_kernel(const float* __restrict__ W2, const float* __restrict__ aW1,
                            const float* __restrict__ b2, const float* __restrict__ ab1,
                            float* __restrict__ C, float* __restrict__ D)
{
    int j = threadIdx.x;   // 0..255
    int k = blockIdx.x;    // 0..128
    if (k < 128) {
        float s = 0.f;
#pragma unroll 8
        for (int t = 0; t < 128; t++) s += W2[k * 128 + t] * aW1[t * 256 + j];
        C[k * 256 + j] = s;
    } else {
        float s = ab1[j];
#pragma unroll 8
        for (int t = 0; t < 128; t++) s += b2[t] * aW1[t * 256 + j];
        D[j] = s;
    }
}

// ---------------- pack C to bf16x2 (k-pairwise) -----------------------------------
__global__ void pack_kernel(const float* __restrict__ C, unsigned* __restrict__ CB)
{
    int kp = blockIdx.x;   // 0..63
    int j = threadIdx.x;   // 0..255
    float lo = C[(2 * kp) * 256 + j];
    float hi = C[(2 * kp + 1) * 256 + j];
    CB[kp * 256 + j] = pack_bf16x2(lo, hi);
}

// ---------------- degree / denom -------------------------------------------------
__global__ void deg_kernel(const int* __restrict__ DST, float* __restrict__ DEG)
{
    int e = blockIdx.x * blockDim.x + threadIdx.x;
    if (e < NE) atomicAdd(&DEG[DST[e]], 1.f);
}

__global__ void dinv_kernel(const float* __restrict__ DEG, float* __restrict__ DINV,
                            float* __restrict__ BM)
{
    int n = blockIdx.x * blockDim.x + threadIdx.x;
    if (n >= NN) return;
    float d = DEG[n];
    DINV[n] = 1.f / fmaxf(d, 1.f);
    BM[n] = (d > 0.f) ? 1.f : 0.f;
}

__global__ void pos_apply_kernel(float* __restrict__ POS, const float* __restrict__ PACC,
                                 const float* __restrict__ DINV, float* __restrict__ outp)
{
    int n = blockIdx.x * blockDim.x + threadIdx.x;
    if (n >= NN) return;
    float di = DINV[n];
#pragma unroll
    for (int i = 0; i < 3; i++) {
        float v = POS[n * 3 + i] + PACC[n * 3 + i] * di;
        POS[n * 3 + i] = v;
        if (outp) outp[n * 3 + i] = v;
    }
}

// ---------------- host ------------------------------------------------------------
extern "C" void kernel_launch(void* const* d_in, const int* in_sizes, int n_in,
                              void* d_out, int out_size)
{
    const float* x        = (const float*)d_in[0];
    const int*   ei32     = (const int*)d_in[1];
    const float* ea       = (const float*)d_in[2];
    const float* pos      = (const float*)d_in[3];
    const float* mW1      = (const float*)d_in[4];
    const float* mb1      = (const float*)d_in[5];
    const float* mW2      = (const float*)d_in[6];
    const float* mb2      = (const float*)d_in[7];
    const float* aW1      = (const float*)d_in[8];
    const float* ab1      = (const float*)d_in[9];
    const float* aW2      = (const float*)d_in[10];
    const float* ab2      = (const float*)d_in[11];
    const float* nW1      = (const float*)d_in[12];
    const float* nb1      = (const float*)d_in[13];
    const float* nW2      = (const float*)d_in[14];
    const float* nb2      = (const float*)d_in[15];
    float* outp = (float*)d_out;

    float *pU, *pV, *pS, *pINTRA, *pHID, *pXA, *pXB, *pPOS, *pPACC;
    float *pDEG, *pDINV, *pBM, *pC, *pD;
    unsigned *pCB;
    int *pSRC, *pDST;
    cudaGetSymbolAddress((void**)&pU, g_U);
    cudaGetSymbolAddress((void**)&pV, g_V);
    cudaGetSymbolAddress((void**)&pS, g_S);
    cudaGetSymbolAddress((void**)&pINTRA, g_INTRA);
    cudaGetSymbolAddress((void**)&pHID, g_HID);
    cudaGetSymbolAddress((void**)&pXA, g_XA);
    cudaGetSymbolAddress((void**)&pXB, g_XB);
    cudaGetSymbolAddress((void**)&pPOS, g_POS);
    cudaGetSymbolAddress((void**)&pPACC, g_POSACC);
    cudaGetSymbolAddress((void**)&pDEG, g_DEG);
    cudaGetSymbolAddress((void**)&pDINV, g_DINV);
    cudaGetSymbolAddress((void**)&pBM, g_BMASK);
    cudaGetSymbolAddress((void**)&pC, g_C);
    cudaGetSymbolAddress((void**)&pCB, g_CB);
    cudaGetSymbolAddress((void**)&pD, g_D);
    cudaGetSymbolAddress((void**)&pSRC, g_SRC);
    cudaGetSymbolAddress((void**)&pDST, g_DST);

    static int attr_done = 0;
    if (!attr_done) {
        cudaFuncSetAttribute(fused_edge, cudaFuncAttributeMaxDynamicSharedMemorySize, FE_SMEM);
        attr_done = 1;
    }

    cudaMemcpyAsync(pPOS, pos, (size_t)NN * 3 * sizeof(float), cudaMemcpyDeviceToDevice);
    convert_idx<<<(NE + 255) / 256, 256>>>(ei32, pSRC, pDST);
    cudaMemsetAsync(pDEG, 0, (size_t)NN * sizeof(float));
    deg_kernel<<<(NE + 255) / 256, 256>>>(pDST, pDEG);
    dinv_kernel<<<(NN + 255) / 256, 256>>>(pDEG, pDINV, pBM);

    const float* xc = x;
    float* xn = pXA;

    for (int l = 0; l < 3; l++) {
        const int last = (l == 2);
        const float* mW1l = mW1 + (long)l * 384 * 128;
        const float* mb1l = mb1 + (long)l * 128;
        const float* mW2l = mW2 + (long)l * 128 * 128;
        const float* mb2l = mb2 + (long)l * 128;
        const float* aW1l = aW1 + (long)l * 128 * 256;
        const float* ab1l = ab1 + (long)l * 256;
        const float* aW2l = aW2 + (long)l * 256;
        const float* ab2l = ab2 + (long)l;
        const float* nW1l = nW1 + (long)l * 256 * 256;
        const float* nb1l = nb1 + (long)l * 256;
        const float* nW2l = nW2 + (long)l * 256 * 128;
        const float* nb2l = nb2 + (long)l * 128;

        if (!last) cudaMemsetAsync(pS, 0, (size_t)NN * HH * sizeof(float));
        cudaMemsetAsync(pPACC, 0, (size_t)NN * 3 * sizeof(float));

        prep_kernel<<<129, 256>>>(mW2l, aW1l, mb2l, ab1l, pC, pD);
        pack_kernel<<<64, 256>>>(pC, pCB);

        dim3 gN(1, (NN + 127) / 128);
        gemm_tf32<<<gN, 256>>>(xc, nullptr, mW1l, nullptr, pU, NN, 128, 128, 0, nullptr, nullptr);
        gemm_tf32<<<gN, 256>>>(xc, nullptr, mW1l + 128 * 128, nullptr, pV, NN, 128, 128, 0, nullptr, nullptr);

        fused_edge<<<(NE + 127) / 128, 256, FE_SMEM>>>(
            ea, mW1l + 256 * 128, mb1l, pU, pV, pSRC, pDST,
            pCB, pD, aW2l, ab2l, pPOS, pS, pPACC, last ? 0 : 1);

        pos_apply_kernel<<<(NN + 255) / 256, 256>>>(pPOS, pPACC, pDINV, last ? outp : nullptr);

        if (!last) {
            gemm_tf32<<<gN, 256>>>(pS, nullptr, mW2l, mb2l, pINTRA, NN, 128, 128, 0, pDINV, pBM);
            dim3 gH(2, (NN + 127) / 128);
            gemm_tf32<<<gH, 256>>>(xc, pINTRA, nW1l, nb1l, pHID, NN, 256, 256, 1, nullptr, nullptr);
            gemm_tf32<<<gN, 256>>>(pHID, nullptr, nW2l, nb2l, xn, NN, 256, 128, 0, nullptr, nullptr);
            xc = xn;
            xn = (xn == pXA) ? pXB : pXA;
        }
    }
}